// round 2
// baseline (speedup 1.0000x reference)
#include <cuda_runtime.h>

// ---------------------------------------------------------------------------
// GCN: out = (segsum(relu(segsum(x[src])@W1 + b1)[src]) ... ) rewritten as:
//   agg1 = segment_sum(x[src], dst)                [N,128]  (CSR gather, no atomics)
//   hp   = relu(agg1 @ W1 + b1) @ W2               [N,64]   (fused MLP)
//   out  = b2 + segment_sum(hp[src], dst)          [N,64]   (CSR gather)
// using the linearity identity segsum(h[src]) @ W == segsum((h@W)[src]).
// CSR (by dst) is rebuilt every replay inside the captured graph.
// ---------------------------------------------------------------------------

#define NMAX 100000
#define EMAX 1600000

__device__ __align__(16) float g_agg1[(size_t)NMAX * 128];
__device__ __align__(16) float g_hp[(size_t)NMAX * 64];
__device__ int g_counts[NMAX];
__device__ int g_rowptr[NMAX];
__device__ int g_cursor[NMAX];
__device__ int g_esrc[EMAX];
__device__ int g_blocksums[1024];

// ---------------- CSR build ----------------

__global__ void k_zero(int N) {
    int i = blockIdx.x * blockDim.x + threadIdx.x;
    if (i < N) g_counts[i] = 0;
}

__global__ void k_hist(const int* __restrict__ dst, int E) {
    int i = blockIdx.x * blockDim.x + threadIdx.x;
    if (i < E) atomicAdd(&g_counts[dst[i]], 1);
}

// per-block exclusive scan of counts -> rowptr; block total -> blocksums
__global__ void k_scan1(int N) {
    __shared__ int s[1024];
    int tid = threadIdx.x;
    int i = blockIdx.x * 1024 + tid;
    int v = (i < N) ? g_counts[i] : 0;
    s[tid] = v;
    __syncthreads();
    #pragma unroll
    for (int off = 1; off < 1024; off <<= 1) {
        int t2 = 0;
        if (tid >= off) t2 = s[tid - off];
        __syncthreads();
        if (tid >= off) s[tid] += t2;
        __syncthreads();
    }
    if (i < N) g_rowptr[i] = s[tid] - v;          // exclusive within block
    if (tid == 1023) g_blocksums[blockIdx.x] = s[tid];  // inclusive block total
}

// exclusive scan of block sums (nb <= 1024)
__global__ void k_scan2(int nb) {
    __shared__ int s[1024];
    int tid = threadIdx.x;
    int v = (tid < nb) ? g_blocksums[tid] : 0;
    s[tid] = v;
    __syncthreads();
    #pragma unroll
    for (int off = 1; off < 1024; off <<= 1) {
        int t2 = 0;
        if (tid >= off) t2 = s[tid - off];
        __syncthreads();
        if (tid >= off) s[tid] += t2;
        __syncthreads();
    }
    if (tid < nb) g_blocksums[tid] = s[tid] - v;  // exclusive
}

__global__ void k_scan3(int N) {
    int i = blockIdx.x * blockDim.x + threadIdx.x;
    if (i < N) {
        int start = g_rowptr[i] + g_blocksums[i >> 10];
        g_rowptr[i] = start;
        g_cursor[i] = start;
    }
}

__global__ void k_fill(const int* __restrict__ src, const int* __restrict__ dst, int E) {
    int i = blockIdx.x * blockDim.x + threadIdx.x;
    if (i < E) {
        int d = dst[i];
        int p = atomicAdd(&g_cursor[d], 1);
        g_esrc[p] = src[i];
    }
}

// ---------------- layer-1 aggregation: warp per node, 128-wide ----------------

__global__ void k_agg1(const float* __restrict__ x, int N) {
    int gw = (blockIdx.x * blockDim.x + threadIdx.x) >> 5;
    int lane = threadIdx.x & 31;
    if (gw >= N) return;
    int beg = g_rowptr[gw];
    int cnt = g_counts[gw];
    float4 acc = make_float4(0.f, 0.f, 0.f, 0.f);
    int j = 0;
    for (; j + 4 <= cnt; j += 4) {
        int s0 = g_esrc[beg + j];
        int s1 = g_esrc[beg + j + 1];
        int s2 = g_esrc[beg + j + 2];
        int s3 = g_esrc[beg + j + 3];
        float4 v0 = *(const float4*)(&x[(size_t)s0 * 128 + lane * 4]);
        float4 v1 = *(const float4*)(&x[(size_t)s1 * 128 + lane * 4]);
        float4 v2 = *(const float4*)(&x[(size_t)s2 * 128 + lane * 4]);
        float4 v3 = *(const float4*)(&x[(size_t)s3 * 128 + lane * 4]);
        acc.x += (v0.x + v1.x) + (v2.x + v3.x);
        acc.y += (v0.y + v1.y) + (v2.y + v3.y);
        acc.z += (v0.z + v1.z) + (v2.z + v3.z);
        acc.w += (v0.w + v1.w) + (v2.w + v3.w);
    }
    for (; j < cnt; j++) {
        int s0 = g_esrc[beg + j];
        float4 v0 = *(const float4*)(&x[(size_t)s0 * 128 + lane * 4]);
        acc.x += v0.x; acc.y += v0.y; acc.z += v0.z; acc.w += v0.w;
    }
    *(float4*)(&g_agg1[(size_t)gw * 128 + lane * 4]) = acc;
}

// ---------------- fused MLP: hp = relu(agg1 @ W1 + b1) @ W2 ----------------
// Block handles BM=32 nodes. Phase 1: 32x128 GEMM (K=128, BK=32 chunks),
// 4x4 register tile per thread. Phase 2: 32x64 GEMM off h in smem.

__global__ __launch_bounds__(256) void k_mlp(const float* __restrict__ W1,
                                             const float* __restrict__ b1,
                                             const float* __restrict__ W2,
                                             int N) {
    __shared__ float smem[6144];          // 24 KB
    float* As  = smem;                    // [32][32]   (phase 1)
    float* Bs  = smem + 1024;             // [32][128]  (phase 1)
    float* Hs  = smem;                    // [32][128]  (phase 2, overlays As/Bs)
    float* W2s = smem + 4096;             // [32][64]   (phase 2)

    int t = threadIdx.x;
    int n0 = blockIdx.x * 32;
    int tn = t & 31;   // 4-col group: cols tn*4..tn*4+3
    int tm = t >> 5;   // 4-row group: rows tm*4..tm*4+3   (== warp id)

    float acc[4][4];
    #pragma unroll
    for (int i = 0; i < 4; i++)
        #pragma unroll
        for (int j = 0; j < 4; j++) acc[i][j] = 0.f;

    #pragma unroll
    for (int kb = 0; kb < 4; kb++) {
        int k0 = kb * 32;
        // load As (32x32): 256 float4, one per thread
        {
            int m = t >> 3;
            int kk = t & 7;
            int row = n0 + m; if (row >= N) row = N - 1;
            *(float4*)(&As[m * 32 + kk * 4]) =
                *(const float4*)(&g_agg1[(size_t)row * 128 + k0 + kk * 4]);
        }
        // load Bs (32x128): 1024 float4, 4 per thread
        #pragma unroll
        for (int r = 0; r < 4; r++) {
            int i = r * 256 + t;
            int k = i >> 5;
            int c4 = i & 31;
            *(float4*)(&Bs[k * 128 + c4 * 4]) =
                *(const float4*)(&W1[(k0 + k) * 128 + c4 * 4]);
        }
        __syncthreads();
        #pragma unroll
        for (int k = 0; k < 32; k += 4) {
            float4 a[4], b[4];
            #pragma unroll
            for (int r = 0; r < 4; r++)
                a[r] = *(float4*)(&As[(tm * 4 + r) * 32 + k]);   // warp-broadcast
            #pragma unroll
            for (int kk = 0; kk < 4; kk++)
                b[kk] = *(float4*)(&Bs[(k + kk) * 128 + tn * 4]);
            #pragma unroll
            for (int r = 0; r < 4; r++) {
                const float* ar = (const float*)&a[r];
                #pragma unroll
                for (int kk = 0; kk < 4; kk++) {
                    acc[r][0] += ar[kk] * b[kk].x;
                    acc[r][1] += ar[kk] * b[kk].y;
                    acc[r][2] += ar[kk] * b[kk].z;
                    acc[r][3] += ar[kk] * b[kk].w;
                }
            }
        }
        __syncthreads();
    }

    // bias + relu -> Hs (overlays As/Bs; safe after the loop-end sync)
    {
        float4 bb = *(const float4*)(&b1[tn * 4]);
        #pragma unroll
        for (int r = 0; r < 4; r++) {
            float4 h;
            h.x = fmaxf(acc[r][0] + bb.x, 0.f);
            h.y = fmaxf(acc[r][1] + bb.y, 0.f);
            h.z = fmaxf(acc[r][2] + bb.z, 0.f);
            h.w = fmaxf(acc[r][3] + bb.w, 0.f);
            *(float4*)(&Hs[(tm * 4 + r) * 128 + tn * 4]) = h;
        }
    }
    __syncthreads();

    // phase 2: hp = Hs(32x128) @ W2(128x64). Thread tile 4 rows x 2 cols.
    int tn2 = t & 31;  // cols tn2*2 .. +1
    int tm2 = t >> 5;  // rows tm2*4 .. +3
    float acc2[4][2];
    #pragma unroll
    for (int r = 0; r < 4; r++) { acc2[r][0] = 0.f; acc2[r][1] = 0.f; }

    #pragma unroll
    for (int kb = 0; kb < 4; kb++) {
        int k0 = kb * 32;
        // load W2s (32x64): 512 float4, 2 per thread
        #pragma unroll
        for (int r = 0; r < 2; r++) {
            int i = r * 256 + t;
            int k = i >> 4;
            int c4 = i & 15;
            *(float4*)(&W2s[k * 64 + c4 * 4]) =
                *(const float4*)(&W2[(k0 + k) * 64 + c4 * 4]);
        }
        __syncthreads();
        #pragma unroll
        for (int k = 0; k < 32; k += 4) {
            float4 a[4];
            float2 b[4];
            #pragma unroll
            for (int r = 0; r < 4; r++)
                a[r] = *(float4*)(&Hs[(tm2 * 4 + r) * 128 + k0 + k]);  // broadcast
            #pragma unroll
            for (int kk = 0; kk < 4; kk++)
                b[kk] = *(float2*)(&W2s[(k + kk) * 64 + tn2 * 2]);
            #pragma unroll
            for (int r = 0; r < 4; r++) {
                const float* ar = (const float*)&a[r];
                #pragma unroll
                for (int kk = 0; kk < 4; kk++) {
                    acc2[r][0] += ar[kk] * b[kk].x;
                    acc2[r][1] += ar[kk] * b[kk].y;
                }
            }
        }
        __syncthreads();
    }

    #pragma unroll
    for (int r = 0; r < 4; r++) {
        int row = n0 + tm2 * 4 + r;
        if (row < N) {
            float2 o = make_float2(acc2[r][0], acc2[r][1]);
            *(float2*)(&g_hp[(size_t)row * 64 + tn2 * 2]) = o;
        }
    }
}

// ---------------- layer-2 aggregation: warp per node, 64-wide, + b2 ----------------

__global__ void k_agg2(const float* __restrict__ b2, float* __restrict__ out, int N) {
    int gw = (blockIdx.x * blockDim.x + threadIdx.x) >> 5;
    int lane = threadIdx.x & 31;
    if (gw >= N) return;
    int beg = g_rowptr[gw];
    int cnt = g_counts[gw];
    float2 acc = *(const float2*)(&b2[lane * 2]);
    int j = 0;
    for (; j + 4 <= cnt; j += 4) {
        int s0 = g_esrc[beg + j];
        int s1 = g_esrc[beg + j + 1];
        int s2 = g_esrc[beg + j + 2];
        int s3 = g_esrc[beg + j + 3];
        float2 v0 = *(const float2*)(&g_hp[(size_t)s0 * 64 + lane * 2]);
        float2 v1 = *(const float2*)(&g_hp[(size_t)s1 * 64 + lane * 2]);
        float2 v2 = *(const float2*)(&g_hp[(size_t)s2 * 64 + lane * 2]);
        float2 v3 = *(const float2*)(&g_hp[(size_t)s3 * 64 + lane * 2]);
        acc.x += (v0.x + v1.x) + (v2.x + v3.x);
        acc.y += (v0.y + v1.y) + (v2.y + v3.y);
    }
    for (; j < cnt; j++) {
        int s0 = g_esrc[beg + j];
        float2 v0 = *(const float2*)(&g_hp[(size_t)s0 * 64 + lane * 2]);
        acc.x += v0.x;
        acc.y += v0.y;
    }
    *(float2*)(&out[(size_t)gw * 64 + lane * 2]) = acc;
}

// ---------------- launch ----------------

extern "C" void kernel_launch(void* const* d_in, const int* in_sizes, int n_in,
                              void* d_out, int out_size) {
    const float* x  = (const float*)d_in[0];
    const int* src  = (const int*)d_in[1];
    const int* dst  = (const int*)d_in[2];
    const float* W1 = (const float*)d_in[3];
    const float* b1 = (const float*)d_in[4];
    const float* W2 = (const float*)d_in[5];
    const float* b2 = (const float*)d_in[6];
    float* out = (float*)d_out;

    int N = in_sizes[0] / 128;
    int E = in_sizes[1];
    int nb = (N + 1023) / 1024;

    k_zero<<<(N + 255) / 256, 256>>>(N);
    k_hist<<<(E + 255) / 256, 256>>>(dst, E);
    k_scan1<<<nb, 1024>>>(N);
    k_scan2<<<1, 1024>>>(nb);
    k_scan3<<<(N + 255) / 256, 256>>>(N);
    k_fill<<<(E + 255) / 256, 256>>>(src, dst, E);

    int warp_blocks = (N * 32 + 255) / 256;      // warp per node
    k_agg1<<<warp_blocks, 256>>>(x, N);
    k_mlp<<<(N + 31) / 32, 256>>>(W1, b1, W2, N);
    k_agg2<<<warp_blocks, 256>>>(b2, out, N);
}